// round 10
// baseline (speedup 1.0000x reference)
#include <cuda_runtime.h>

#define N_NODES 50000
#define N_EDGES 800000
#define N_LABEL 200000
#define FEAT 128
#define HID 32
#define HEADS 8
#define H1 256   // HEADS*HID
#define SCAN_BLOCKS 196  // 196*256 = 50176 >= N_NODES

// ---------------- scratch (device globals; no allocation) ----------------
__device__ __align__(16) float g_h0 [N_NODES * HID];
__device__ __align__(16) float g_as1[N_NODES * HEADS];
__device__ __align__(16) float g_ad1[N_NODES * HEADS];
__device__ __align__(16) float g_xs2[N_NODES * HID];
__device__ __align__(16) float g_as2[N_NODES];
__device__ __align__(16) float g_ad2[N_NODES];
__device__ __align__(16) float g_out2[N_NODES * HID];
__device__ __align__(16) float g_v1d[HID * HEADS];
__device__ __align__(16) float g_v1s[HID * HEADS];
__device__ __align__(16) float g_v2d[H1];
// CSR build
__device__ int g_cnt[N_NODES];     // zero-initialized at load; re-zeroed by k_pred each replay
__device__ int g_loc[N_NODES];
__device__ int g_bsum[256];
__device__ int g_boff[256];
__device__ int g_rowptr[N_NODES + 1];
__device__ int g_cur[N_NODES];
__device__ int g_perm_src[N_EDGES];

__device__ __forceinline__ float lrelu_exp(float a) {
    float l = a > 0.f ? a : 0.2f * a;
    return __expf(l);
}

// ---------------- K_hist: 4-edge unroll for MLP ----------------
__global__ void k_hist(const int* __restrict__ ei) {
    int base = blockIdx.x * 1024 + threadIdx.x;
    #pragma unroll
    for (int u = 0; u < 4; u++) {
        int e = base + u * 256;
        if (e < N_EDGES) atomicAdd(&g_cnt[__ldg(&ei[N_EDGES + e])], 1);
    }
}

// ---------------- K_scan1: per-block inclusive scan of g_cnt ----------------
__global__ void k_scan1() {
    int t = threadIdx.x, b = blockIdx.x;
    int i = b * 256 + t;
    int lane = t & 31, warp = t >> 5;
    int v = (i < N_NODES) ? g_cnt[i] : 0;
    int x = v;
    #pragma unroll
    for (int off = 1; off < 32; off <<= 1) {
        int y = __shfl_up_sync(0xffffffffu, x, off);
        if (lane >= off) x += y;
    }
    __shared__ int ws[8];
    if (lane == 31) ws[warp] = x;
    __syncthreads();
    if (t < 8) {
        int y = ws[t];
        #pragma unroll
        for (int off = 1; off < 8; off <<= 1) {
            int z = __shfl_up_sync(0x000000ffu, y, off);
            if (t >= off) y += z;
        }
        ws[t] = y;
    }
    __syncthreads();
    if (warp > 0) x += ws[warp - 1];
    if (i < N_NODES) g_loc[i] = x;
    if (t == 255) g_bsum[b] = x;
}

// ---------------- K_scan2: scan block sums (1 block) + prep folds ----------------
__global__ void k_scan2(const float* __restrict__ w1d, const float* __restrict__ a1d,
                        const float* __restrict__ w1s, const float* __restrict__ a1s,
                        const float* __restrict__ w2d, const float* __restrict__ a2d) {
    int t = threadIdx.x;  // 256
    int lane = t & 31, warp = t >> 5;
    int v = (t < SCAN_BLOCKS) ? g_bsum[t] : 0;
    int x = v;
    #pragma unroll
    for (int off = 1; off < 32; off <<= 1) {
        int y = __shfl_up_sync(0xffffffffu, x, off);
        if (lane >= off) x += y;
    }
    __shared__ int ws[8];
    if (lane == 31) ws[warp] = x;
    __syncthreads();
    if (t < 8) {
        int y = ws[t];
        #pragma unroll
        for (int off = 1; off < 8; off <<= 1) {
            int z = __shfl_up_sync(0x000000ffu, y, off);
            if (t >= off) y += z;
        }
        ws[t] = y;
    }
    __syncthreads();
    if (warp > 0) x += ws[warp - 1];
    g_boff[t] = x - v;

    {
        int k = t >> 3, h = t & 7;
        float d = 0.f, s = 0.f;
        #pragma unroll
        for (int c = 0; c < HID; c++) {
            d += w1d[k * H1 + h * HID + c] * a1d[h * HID + c];
            s += w1s[k * H1 + h * HID + c] * a1s[h * HID + c];
        }
        g_v1d[k * HEADS + h] = d;
        g_v1s[k * HEADS + h] = s;
    }
    {
        float s = 0.f;
        #pragma unroll
        for (int c = 0; c < HID; c++) s += w2d[t * HID + c] * a2d[c];
        g_v2d[t] = s;
    }
}

// ---------------- K_lin: tiled GEMM 128 nodes x 32 ch, thread = 4n x 4c ----------------
#define XPITCH 65
#define KCHUNK 64
__global__ void k_lin(const float* __restrict__ x, const float* __restrict__ w,
                      const float* __restrict__ b) {
    __shared__ __align__(16) float Ws[FEAT * HID];
    __shared__ float Xs[128 * XPITCH];
    __shared__ float Vds[16 * HID];
    int tid = threadIdx.x;  // 256
    int nb = blockIdx.x * 128;

    for (int i = tid; i < FEAT * HID / 4; i += 256)
        ((float4*)Ws)[i] = ((const float4*)w)[i];
    for (int i = tid; i < HID * HEADS; i += 256) {
        int c = i >> 3, h = i & 7;
        Vds[h * HID + c]       = g_v1d[c * HEADS + h];
        Vds[(8 + h) * HID + c] = g_v1s[c * HEADS + h];
    }
    if (tid < 128) {
        int node = nb + tid;
        if (node < N_NODES) {
            int e = g_loc[node] - g_cnt[node] + g_boff[node >> 8];
            g_rowptr[node] = e;
            g_cur[node] = e;
            if (node == 0) g_rowptr[N_NODES] = N_EDGES;
        }
    }

    int c4 = (tid & 7) * 4;
    int nr = (tid >> 3) * 4;
    float4 acc0 = {0,0,0,0}, acc1 = {0,0,0,0}, acc2 = {0,0,0,0}, acc3 = {0,0,0,0};

    #pragma unroll
    for (int chunk = 0; chunk < FEAT / KCHUNK; chunk++) {
        __syncthreads();
        for (int i = tid; i < 128 * (KCHUNK / 4); i += 256) {
            int row = i >> 4, kq = i & 15;
            int n = nb + row;
            float4 v = make_float4(0.f, 0.f, 0.f, 0.f);
            if (n < N_NODES)
                v = *(const float4*)&x[(size_t)n * FEAT + chunk * KCHUNK + kq * 4];
            float* dst = &Xs[row * XPITCH + kq * 4];
            dst[0] = v.x; dst[1] = v.y; dst[2] = v.z; dst[3] = v.w;
        }
        __syncthreads();
        #pragma unroll 16
        for (int kk = 0; kk < KCHUNK; kk++) {
            int k = chunk * KCHUNK + kk;
            float4 wv = *(const float4*)&Ws[k * HID + c4];
            float x0 = Xs[(nr + 0) * XPITCH + kk];
            float x1 = Xs[(nr + 1) * XPITCH + kk];
            float x2 = Xs[(nr + 2) * XPITCH + kk];
            float x3 = Xs[(nr + 3) * XPITCH + kk];
            acc0.x += x0 * wv.x; acc0.y += x0 * wv.y; acc0.z += x0 * wv.z; acc0.w += x0 * wv.w;
            acc1.x += x1 * wv.x; acc1.y += x1 * wv.y; acc1.z += x1 * wv.z; acc1.w += x1 * wv.w;
            acc2.x += x2 * wv.x; acc2.y += x2 * wv.y; acc2.z += x2 * wv.z; acc2.w += x2 * wv.w;
            acc3.x += x3 * wv.x; acc3.y += x3 * wv.y; acc3.z += x3 * wv.z; acc3.w += x3 * wv.w;
        }
    }

    float4 bb = *(const float4*)&b[c4];
    float4 hv[4];
    hv[0].x = acc0.x + bb.x; hv[0].y = acc0.y + bb.y; hv[0].z = acc0.z + bb.z; hv[0].w = acc0.w + bb.w;
    hv[1].x = acc1.x + bb.x; hv[1].y = acc1.y + bb.y; hv[1].z = acc1.z + bb.z; hv[1].w = acc1.w + bb.w;
    hv[2].x = acc2.x + bb.x; hv[2].y = acc2.y + bb.y; hv[2].z = acc2.z + bb.z; hv[2].w = acc2.w + bb.w;
    hv[3].x = acc3.x + bb.x; hv[3].y = acc3.y + bb.y; hv[3].z = acc3.z + bb.z; hv[3].w = acc3.w + bb.w;
    int lane = tid & 31;
    bool leader = (lane & 7) == 0;
    #pragma unroll
    for (int i = 0; i < 4; i++) {
        int n = nb + nr + i;
        bool valid = n < N_NODES;
        if (valid) *(float4*)&g_h0[n * HID + c4] = hv[i];
        #pragma unroll
        for (int h = 0; h < 8; h++) {
            const float* vd = &Vds[h * HID + c4];
            const float* vs = &Vds[(8 + h) * HID + c4];
            float d = hv[i].x * vd[0] + hv[i].y * vd[1] + hv[i].z * vd[2] + hv[i].w * vd[3];
            float s = hv[i].x * vs[0] + hv[i].y * vs[1] + hv[i].z * vs[2] + hv[i].w * vs[3];
            #pragma unroll
            for (int off = 4; off; off >>= 1) {
                d += __shfl_xor_sync(0xffffffffu, d, off);
                s += __shfl_xor_sync(0xffffffffu, s, off);
            }
            if (valid && leader) {
                g_ad1[n * HEADS + h] = d;
                g_as1[n * HEADS + h] = s;
            }
        }
    }
}

// ---------------- K_permute: 4-edge unroll ----------------
__global__ void k_permute(const int* __restrict__ ei) {
    int base = blockIdx.x * 1024 + threadIdx.x;
    #pragma unroll
    for (int u = 0; u < 4; u++) {
        int e = base + u * 256;
        if (e < N_EDGES) {
            int src = __ldg(&ei[e]);
            int dst = __ldg(&ei[N_EDGES + e]);
            int pos = atomicAdd(&g_cur[dst], 1);
            g_perm_src[pos] = src;
        }
    }
}

// ---------------- K_agg1 FUSED: gather -> h1 (smem only) -> xs2/as2/ad2 ----------------
// 512 threads = 16 warps = 16 nodes per block. out1 never touches gmem.
#define G2PITCH (H1 + 4)   // 260
__global__ void k_agg1(const float* __restrict__ w1s, const float* __restrict__ b1,
                       const float* __restrict__ w2s, const float* __restrict__ a2s) {
    __shared__ float s_t [16][H1];                      // 16KB normalized aggregate per head
    __shared__ float s_h1[16][H1];                      // 16KB h1 tile
    __shared__ __align__(16) float WsT[HID * G2PITCH];  // 33KB w2s transposed [c][co]
    __shared__ float s_pd[16][8];
    int tid = threadIdx.x;
    int warp = tid >> 5, lane = tid & 31;

    // stage w2s transposed
    for (int i = tid; i < H1 * HID; i += 512) {
        int co = i >> 5, c = i & 31;
        WsT[c * G2PITCH + co] = w2s[i];
    }

    // ---- phase 1: warp-per-node weighted h0 gather (deferred normalization) ----
    int n = blockIdx.x * 16 + warp;   // N_NODES % 16 == 0
    int beg = g_rowptr[n], end = g_rowptr[n + 1];
    float ad_l = (lane < 16) ? g_ad1[n * 8 + (lane & 7)] : 0.f;
    float den = 0.f;
    float acc[8] = {0, 0, 0, 0, 0, 0, 0, 0};
    int p = beg;
    for (; p + 2 <= end; p += 2) {
        int s0 = __ldg(&g_perm_src[p]);
        int s1 = __ldg(&g_perm_src[p + 1]);
        float e = 0.f;
        if (lane < 8)       e = lrelu_exp(__ldg(&g_as1[s0 * 8 + lane]) + ad_l);
        else if (lane < 16) e = lrelu_exp(__ldg(&g_as1[s1 * 8 + (lane - 8)]) + ad_l);
        den += e;
        float h0a = g_h0[s0 * HID + lane];
        float h0b = g_h0[s1 * HID + lane];
        #pragma unroll
        for (int h = 0; h < 8; h++) {
            float e0 = __shfl_sync(0xffffffffu, e, h);
            float e1 = __shfl_sync(0xffffffffu, e, h + 8);
            acc[h] += e0 * h0a + e1 * h0b;
        }
    }
    if (p < end) {
        int s0 = __ldg(&g_perm_src[p]);
        float e = 0.f;
        if (lane < 8) e = lrelu_exp(__ldg(&g_as1[s0 * 8 + lane]) + ad_l);
        den += e;
        float h0a = g_h0[s0 * HID + lane];
        #pragma unroll
        for (int h = 0; h < 8; h++) {
            float e0 = __shfl_sync(0xffffffffu, e, h);
            acc[h] += e0 * h0a;
        }
    }
    float dsum = den + __shfl_xor_sync(0xffffffffu, den, 8);
    #pragma unroll
    for (int h = 0; h < 8; h++) {
        float dh = __shfl_sync(0xffffffffu, dsum, h);
        s_t[warp][h * HID + lane] = acc[h] * (1.0f / (dh + 1e-16f));
    }
    __syncthreads();

    // ---- phase 2: h1 = relu(t @ w1s + b1) into s_h1; ad2 partials ----
    int co = tid & 255;
    int half = tid >> 8;            // node half 0/1
    int hh = co >> 5;
    float wcol[HID];
    #pragma unroll
    for (int k = 0; k < HID; k++) wcol[k] = __ldg(&w1s[k * H1 + co]);
    float bb = b1[co];
    float vv = g_v2d[co];
    float pds[8];
    #pragma unroll
    for (int i = 0; i < 8; i++) {
        int ni = half * 8 + i;
        const float4* tp = (const float4*)&s_t[ni][hh * HID];
        float a = bb;
        #pragma unroll
        for (int k4 = 0; k4 < HID / 4; k4++) {
            float4 tv = tp[k4];
            int k = k4 * 4;
            a += tv.x * wcol[k + 0] + tv.y * wcol[k + 1]
               + tv.z * wcol[k + 2] + tv.w * wcol[k + 3];
        }
        a = fmaxf(a, 0.f);
        s_h1[ni][co] = a;
        pds[i] = a * vv;
    }
    #pragma unroll
    for (int i = 0; i < 8; i++) {
        float v = pds[i];
        #pragma unroll
        for (int off = 16; off; off >>= 1) v += __shfl_down_sync(0xffffffffu, v, off);
        if (lane == 0) s_pd[warp][i] = v;
    }
    __syncthreads();
    if (tid < 16) {
        int hf = tid >> 3;
        float s = 0.f;
        #pragma unroll
        for (int w = 0; w < 8; w++) s += s_pd[hf * 8 + w][tid & 7];
        g_ad2[blockIdx.x * 16 + tid] = s;
    }

    // ---- phase 3: xs2 = h1 @ w2s; as2 ----
    int nodei = tid >> 5;           // 0..15 (== warp)
    int c = tid & 31;
    const float4* hp = (const float4*)&s_h1[nodei][0];
    const float4* wp = (const float4*)&WsT[c * G2PITCH];
    float a2 = 0.f;
    #pragma unroll 16
    for (int co4 = 0; co4 < H1 / 4; co4++) {
        float4 hx = hp[co4];
        float4 wv = wp[co4];
        a2 += hx.x * wv.x + hx.y * wv.y + hx.z * wv.z + hx.w * wv.w;
    }
    int n2 = blockIdx.x * 16 + nodei;
    g_xs2[n2 * HID + c] = a2;
    float ps = a2 * a2s[c];
    #pragma unroll
    for (int off = 16; off; off >>= 1) ps += __shfl_down_sync(0xffffffffu, ps, off);
    if (c == 0) g_as2[n2] = ps;
}

// ---------------- K_agg2: single-pass deferred-normalization gather (+b2) ----------------
__global__ void k_agg2(const float* __restrict__ b2) {
    int lane = threadIdx.x & 31;
    int n = blockIdx.x * 8 + (threadIdx.x >> 5);
    if (n >= N_NODES) return;
    int beg = g_rowptr[n], end = g_rowptr[n + 1];
    float adn = g_ad2[n];
    int k = lane >> 3, j = lane & 7;
    float4 acc = {0, 0, 0, 0};
    float den = 0.f;
    int p = beg + k;
    for (; p + 12 < end; p += 16) {
        int s0 = __ldg(&g_perm_src[p]);
        int s1 = __ldg(&g_perm_src[p + 4]);
        int s2 = __ldg(&g_perm_src[p + 8]);
        int s3 = __ldg(&g_perm_src[p + 12]);
        float e0 = lrelu_exp(__ldg(&g_as2[s0]) + adn);
        float e1 = lrelu_exp(__ldg(&g_as2[s1]) + adn);
        float e2 = lrelu_exp(__ldg(&g_as2[s2]) + adn);
        float e3 = lrelu_exp(__ldg(&g_as2[s3]) + adn);
        float4 v0 = *(const float4*)&g_xs2[s0 * HID + j * 4];
        float4 v1 = *(const float4*)&g_xs2[s1 * HID + j * 4];
        float4 v2 = *(const float4*)&g_xs2[s2 * HID + j * 4];
        float4 v3 = *(const float4*)&g_xs2[s3 * HID + j * 4];
        den += (e0 + e1) + (e2 + e3);
        acc.x += v0.x * e0 + v1.x * e1 + v2.x * e2 + v3.x * e3;
        acc.y += v0.y * e0 + v1.y * e1 + v2.y * e2 + v3.y * e3;
        acc.z += v0.z * e0 + v1.z * e1 + v2.z * e2 + v3.z * e3;
        acc.w += v0.w * e0 + v1.w * e1 + v2.w * e2 + v3.w * e3;
    }
    for (; p < end; p += 4) {
        int s0 = __ldg(&g_perm_src[p]);
        float e0 = lrelu_exp(__ldg(&g_as2[s0]) + adn);
        float4 v0 = *(const float4*)&g_xs2[s0 * HID + j * 4];
        den += e0;
        acc.x += v0.x * e0; acc.y += v0.y * e0;
        acc.z += v0.z * e0; acc.w += v0.w * e0;
    }
    #pragma unroll
    for (int off = 8; off <= 16; off <<= 1) {
        acc.x += __shfl_xor_sync(0xffffffffu, acc.x, off);
        acc.y += __shfl_xor_sync(0xffffffffu, acc.y, off);
        acc.z += __shfl_xor_sync(0xffffffffu, acc.z, off);
        acc.w += __shfl_xor_sync(0xffffffffu, acc.w, off);
        den   += __shfl_xor_sync(0xffffffffu, den,   off);
    }
    if (lane < 8) {
        float r = 1.0f / (den + 1e-16f);
        float4 bb = *(const float4*)&b2[j * 4];
        acc.x = acc.x * r + bb.x; acc.y = acc.y * r + bb.y;
        acc.z = acc.z * r + bb.z; acc.w = acc.w * r + bb.w;
        *(float4*)&g_out2[n * HID + j * 4] = acc;
    }
}

// ---------------- K_pred (+ re-zero g_cnt for next replay) ----------------
__global__ void k_pred(const int* __restrict__ eli, float* __restrict__ out) {
    int l = blockIdx.x * blockDim.x + threadIdx.x;
    if (l < N_NODES) g_cnt[l] = 0;
    if (l >= N_LABEL) return;
    int a = eli[l], b = eli[N_LABEL + l];
    const float4* pa = (const float4*)&g_out2[a * HID];
    const float4* pb = (const float4*)&g_out2[b * HID];
    float acc = 0.f;
    #pragma unroll
    for (int i = 0; i < HID / 4; i++) {
        float4 va = pa[i], vb = pb[i];
        acc += va.x * vb.x + va.y * vb.y + va.z * vb.z + va.w * vb.w;
    }
    out[l] = acc;
}

// ---------------- launch ----------------
extern "C" void kernel_launch(void* const* d_in, const int* in_sizes, int n_in,
                              void* d_out, int out_size) {
    const float* x     = (const float*)d_in[0];
    const int*   ei    = (const int*)  d_in[1];
    const int*   eli   = (const int*)  d_in[2];
    const float* lin_w = (const float*)d_in[3];
    const float* lin_b = (const float*)d_in[4];
    const float* w1s   = (const float*)d_in[5];
    const float* w1d   = (const float*)d_in[6];
    const float* a1s   = (const float*)d_in[7];
    const float* a1d   = (const float*)d_in[8];
    const float* b1    = (const float*)d_in[9];
    const float* w2s   = (const float*)d_in[10];
    const float* w2d   = (const float*)d_in[11];
    const float* a2s   = (const float*)d_in[12];
    const float* a2d   = (const float*)d_in[13];
    const float* b2    = (const float*)d_in[14];
    float* out = (float*)d_out;

    k_hist<<<(N_EDGES + 1023) / 1024, 256>>>(ei);
    k_scan1<<<SCAN_BLOCKS, 256>>>();
    k_scan2<<<1, 256>>>(w1d, a1d, w1s, a1s, w2d, a2d);
    k_lin<<<(N_NODES + 127) / 128, 256>>>(x, lin_w, lin_b);   // 4th launch -> profiled
    k_permute<<<(N_EDGES + 1023) / 1024, 256>>>(ei);
    k_agg1<<<N_NODES / 16, 512>>>(w1s, b1, w2s, a2s);
    k_agg2<<<(N_NODES + 7) / 8, 256>>>(b2);
    k_pred<<<(N_LABEL + 255) / 256, 256>>>(eli, out);
}

// round 11
// speedup vs baseline: 1.0878x; 1.0878x over previous
#include <cuda_runtime.h>

#define N_NODES 50000
#define N_EDGES 800000
#define N_LABEL 200000
#define FEAT 128
#define HID 32
#define HEADS 8
#define H1 256   // HEADS*HID
#define SCAN_BLOCKS 196  // 196*256 = 50176 >= N_NODES

// ---------------- scratch (device globals; no allocation) ----------------
__device__ __align__(16) float g_h0 [N_NODES * HID];
__device__ __align__(16) float g_as1[N_NODES * HEADS];
__device__ __align__(16) float g_ad1[N_NODES * HEADS];
__device__ __align__(16) float g_out1[N_NODES * H1];
__device__ __align__(16) float g_xs2[N_NODES * HID];
__device__ __align__(16) float g_as2[N_NODES];
__device__ __align__(16) float g_ad2[N_NODES];
__device__ __align__(16) float g_out2[N_NODES * HID];
__device__ __align__(16) float g_v1d[HID * HEADS];
__device__ __align__(16) float g_v1s[HID * HEADS];
__device__ __align__(16) float g_v2d[H1];
// CSR build
__device__ int g_cnt[N_NODES];     // zero-initialized at load; re-zeroed by k_pred each replay
__device__ int g_loc[N_NODES];
__device__ int g_bsum[256];
__device__ int g_boff[256];
__device__ int g_rowptr[N_NODES + 1];
__device__ int g_cur[N_NODES];
__device__ int g_perm_src[N_EDGES];

__device__ __forceinline__ float lrelu_exp(float a) {
    float l = a > 0.f ? a : 0.2f * a;
    return __expf(l);
}

// ---------------- K_hist ----------------
__global__ void k_hist(const int* __restrict__ ei) {
    int base = blockIdx.x * 1024 + threadIdx.x;
    #pragma unroll
    for (int u = 0; u < 4; u++) {
        int e = base + u * 256;
        if (e < N_EDGES) atomicAdd(&g_cnt[__ldg(&ei[N_EDGES + e])], 1);
    }
}

// ---------------- K_scan1 ----------------
__global__ void k_scan1() {
    int t = threadIdx.x, b = blockIdx.x;
    int i = b * 256 + t;
    int lane = t & 31, warp = t >> 5;
    int v = (i < N_NODES) ? g_cnt[i] : 0;
    int x = v;
    #pragma unroll
    for (int off = 1; off < 32; off <<= 1) {
        int y = __shfl_up_sync(0xffffffffu, x, off);
        if (lane >= off) x += y;
    }
    __shared__ int ws[8];
    if (lane == 31) ws[warp] = x;
    __syncthreads();
    if (t < 8) {
        int y = ws[t];
        #pragma unroll
        for (int off = 1; off < 8; off <<= 1) {
            int z = __shfl_up_sync(0x000000ffu, y, off);
            if (t >= off) y += z;
        }
        ws[t] = y;
    }
    __syncthreads();
    if (warp > 0) x += ws[warp - 1];
    if (i < N_NODES) g_loc[i] = x;
    if (t == 255) g_bsum[b] = x;
}

// ---------------- K_scan2: scan block sums (1 block) ----------------
__global__ void k_scan2() {
    int t = threadIdx.x;  // 256
    int lane = t & 31, warp = t >> 5;
    int v = (t < SCAN_BLOCKS) ? g_bsum[t] : 0;
    int x = v;
    #pragma unroll
    for (int off = 1; off < 32; off <<= 1) {
        int y = __shfl_up_sync(0xffffffffu, x, off);
        if (lane >= off) x += y;
    }
    __shared__ int ws[8];
    if (lane == 31) ws[warp] = x;
    __syncthreads();
    if (t < 8) {
        int y = ws[t];
        #pragma unroll
        for (int off = 1; off < 8; off <<= 1) {
            int z = __shfl_up_sync(0x000000ffu, y, off);
            if (t >= off) y += z;
        }
        ws[t] = y;
    }
    __syncthreads();
    if (warp > 0) x += ws[warp - 1];
    g_boff[t] = x - v;
}

// ---------------- K_scan3: finalize rowptr/cur ----------------
__global__ void k_scan3() {
    int i = blockIdx.x * 256 + threadIdx.x;
    if (i < N_NODES) {
        int e = g_loc[i] - g_cnt[i] + g_boff[i >> 8];
        g_rowptr[i] = e;
        g_cur[i] = e;
        if (i == 0) g_rowptr[N_NODES] = N_EDGES;
    }
}

// ---------------- K_prep: fold projections with attention vectors ----------------
__global__ void k_prep(const float* __restrict__ w1d, const float* __restrict__ a1d,
                       const float* __restrict__ w1s, const float* __restrict__ a1s,
                       const float* __restrict__ w2d, const float* __restrict__ a2d) {
    int t = threadIdx.x;  // 256
    {
        int k = t >> 3, h = t & 7;
        float d = 0.f, s = 0.f;
        #pragma unroll
        for (int c = 0; c < HID; c++) {
            d += w1d[k * H1 + h * HID + c] * a1d[h * HID + c];
            s += w1s[k * H1 + h * HID + c] * a1s[h * HID + c];
        }
        g_v1d[k * HEADS + h] = d;
        g_v1s[k * HEADS + h] = s;
    }
    {
        float s = 0.f;
        #pragma unroll
        for (int c = 0; c < HID; c++) s += w2d[t * HID + c] * a2d[c];
        g_v2d[t] = s;
    }
}

// ---------------- K_lin: tiled GEMM 128 nodes x 32 ch, thread = 4n x 4c ----------------
#define XPITCH 65
#define KCHUNK 64
__global__ void k_lin(const float* __restrict__ x, const float* __restrict__ w,
                      const float* __restrict__ b) {
    __shared__ __align__(16) float Ws[FEAT * HID];
    __shared__ float Xs[128 * XPITCH];
    __shared__ float Vds[16 * HID];
    int tid = threadIdx.x;  // 256
    int nb = blockIdx.x * 128;

    for (int i = tid; i < FEAT * HID / 4; i += 256)
        ((float4*)Ws)[i] = ((const float4*)w)[i];
    for (int i = tid; i < HID * HEADS; i += 256) {
        int c = i >> 3, h = i & 7;
        Vds[h * HID + c]       = g_v1d[c * HEADS + h];
        Vds[(8 + h) * HID + c] = g_v1s[c * HEADS + h];
    }

    int c4 = (tid & 7) * 4;
    int nr = (tid >> 3) * 4;
    float4 acc0 = {0,0,0,0}, acc1 = {0,0,0,0}, acc2 = {0,0,0,0}, acc3 = {0,0,0,0};

    #pragma unroll
    for (int chunk = 0; chunk < FEAT / KCHUNK; chunk++) {
        __syncthreads();
        for (int i = tid; i < 128 * (KCHUNK / 4); i += 256) {
            int row = i >> 4, kq = i & 15;
            int n = nb + row;
            float4 v = make_float4(0.f, 0.f, 0.f, 0.f);
            if (n < N_NODES)
                v = *(const float4*)&x[(size_t)n * FEAT + chunk * KCHUNK + kq * 4];
            float* dst = &Xs[row * XPITCH + kq * 4];
            dst[0] = v.x; dst[1] = v.y; dst[2] = v.z; dst[3] = v.w;
        }
        __syncthreads();
        #pragma unroll 16
        for (int kk = 0; kk < KCHUNK; kk++) {
            int k = chunk * KCHUNK + kk;
            float4 wv = *(const float4*)&Ws[k * HID + c4];
            float x0 = Xs[(nr + 0) * XPITCH + kk];
            float x1 = Xs[(nr + 1) * XPITCH + kk];
            float x2 = Xs[(nr + 2) * XPITCH + kk];
            float x3 = Xs[(nr + 3) * XPITCH + kk];
            acc0.x += x0 * wv.x; acc0.y += x0 * wv.y; acc0.z += x0 * wv.z; acc0.w += x0 * wv.w;
            acc1.x += x1 * wv.x; acc1.y += x1 * wv.y; acc1.z += x1 * wv.z; acc1.w += x1 * wv.w;
            acc2.x += x2 * wv.x; acc2.y += x2 * wv.y; acc2.z += x2 * wv.z; acc2.w += x2 * wv.w;
            acc3.x += x3 * wv.x; acc3.y += x3 * wv.y; acc3.z += x3 * wv.z; acc3.w += x3 * wv.w;
        }
    }

    float4 bb = *(const float4*)&b[c4];
    float4 hv[4];
    hv[0].x = acc0.x + bb.x; hv[0].y = acc0.y + bb.y; hv[0].z = acc0.z + bb.z; hv[0].w = acc0.w + bb.w;
    hv[1].x = acc1.x + bb.x; hv[1].y = acc1.y + bb.y; hv[1].z = acc1.z + bb.z; hv[1].w = acc1.w + bb.w;
    hv[2].x = acc2.x + bb.x; hv[2].y = acc2.y + bb.y; hv[2].z = acc2.z + bb.z; hv[2].w = acc2.w + bb.w;
    hv[3].x = acc3.x + bb.x; hv[3].y = acc3.y + bb.y; hv[3].z = acc3.z + bb.z; hv[3].w = acc3.w + bb.w;
    int lane = tid & 31;
    bool leader = (lane & 7) == 0;
    #pragma unroll
    for (int i = 0; i < 4; i++) {
        int n = nb + nr + i;
        bool valid = n < N_NODES;
        if (valid) *(float4*)&g_h0[n * HID + c4] = hv[i];
        #pragma unroll
        for (int h = 0; h < 8; h++) {
            const float* vd = &Vds[h * HID + c4];
            const float* vs = &Vds[(8 + h) * HID + c4];
            float d = hv[i].x * vd[0] + hv[i].y * vd[1] + hv[i].z * vd[2] + hv[i].w * vd[3];
            float s = hv[i].x * vs[0] + hv[i].y * vs[1] + hv[i].z * vs[2] + hv[i].w * vs[3];
            #pragma unroll
            for (int off = 4; off; off >>= 1) {
                d += __shfl_xor_sync(0xffffffffu, d, off);
                s += __shfl_xor_sync(0xffffffffu, s, off);
            }
            if (valid && leader) {
                g_ad1[n * HEADS + h] = d;
                g_as1[n * HEADS + h] = s;
            }
        }
    }
}

// ---------------- K_permute ----------------
__global__ void k_permute(const int* __restrict__ ei) {
    int base = blockIdx.x * 1024 + threadIdx.x;
    #pragma unroll
    for (int u = 0; u < 4; u++) {
        int e = base + u * 256;
        if (e < N_EDGES) {
            int src = __ldg(&ei[e]);
            int dst = __ldg(&ei[N_EDGES + e]);
            int pos = atomicAdd(&g_cur[dst], 1);
            g_perm_src[pos] = src;
        }
    }
}

// ---------------- K_agg1 (R9): warp/node h0-aggregation, then per-head GEMM -> out1 ----------------
__global__ void k_agg1(const float* __restrict__ w1s, const float* __restrict__ b1) {
    __shared__ float s_t[8][H1];
    __shared__ float s_pd[8][8];
    int tid = threadIdx.x;
    int warp = tid >> 5, lane = tid & 31;
    int n = blockIdx.x * 8 + warp;   // N_NODES % 8 == 0
    int beg = g_rowptr[n], end = g_rowptr[n + 1];
    float ad_l = (lane < 16) ? g_ad1[n * 8 + (lane & 7)] : 0.f;

    float den = 0.f;
    float acc[8] = {0, 0, 0, 0, 0, 0, 0, 0};
    int p = beg;
    for (; p + 2 <= end; p += 2) {
        int s0 = __ldg(&g_perm_src[p]);
        int s1 = __ldg(&g_perm_src[p + 1]);
        float e = 0.f;
        if (lane < 8)       e = lrelu_exp(__ldg(&g_as1[s0 * 8 + lane]) + ad_l);
        else if (lane < 16) e = lrelu_exp(__ldg(&g_as1[s1 * 8 + (lane - 8)]) + ad_l);
        den += e;
        float h0a = g_h0[s0 * HID + lane];
        float h0b = g_h0[s1 * HID + lane];
        #pragma unroll
        for (int h = 0; h < 8; h++) {
            float e0 = __shfl_sync(0xffffffffu, e, h);
            float e1 = __shfl_sync(0xffffffffu, e, h + 8);
            acc[h] += e0 * h0a + e1 * h0b;
        }
    }
    if (p < end) {
        int s0 = __ldg(&g_perm_src[p]);
        float e = 0.f;
        if (lane < 8) e = lrelu_exp(__ldg(&g_as1[s0 * 8 + lane]) + ad_l);
        den += e;
        float h0a = g_h0[s0 * HID + lane];
        #pragma unroll
        for (int h = 0; h < 8; h++) {
            float e0 = __shfl_sync(0xffffffffu, e, h);
            acc[h] += e0 * h0a;
        }
    }
    float dsum = den + __shfl_xor_sync(0xffffffffu, den, 8);
    #pragma unroll
    for (int h = 0; h < 8; h++) {
        float dh = __shfl_sync(0xffffffffu, dsum, h);
        s_t[warp][h * HID + lane] = acc[h] * (1.0f / (dh + 1e-16f));
    }
    __syncthreads();

    int co = tid;
    int hh = co >> 5;
    float wcol[HID];
    #pragma unroll
    for (int k = 0; k < HID; k++) wcol[k] = __ldg(&w1s[k * H1 + co]);
    float bb = b1[co];
    float vv = g_v2d[co];
    float pds[8];
    #pragma unroll
    for (int i = 0; i < 8; i++) {
        const float4* tp = (const float4*)&s_t[i][hh * HID];
        float a = bb;
        #pragma unroll
        for (int k4 = 0; k4 < HID / 4; k4++) {
            float4 tv = tp[k4];
            int k = k4 * 4;
            a += tv.x * wcol[k + 0] + tv.y * wcol[k + 1]
               + tv.z * wcol[k + 2] + tv.w * wcol[k + 3];
        }
        a = fmaxf(a, 0.f);
        g_out1[(blockIdx.x * 8 + i) * H1 + co] = a;
        pds[i] = a * vv;
    }
    #pragma unroll
    for (int i = 0; i < 8; i++) {
        float v = pds[i];
        #pragma unroll
        for (int off = 16; off; off >>= 1) v += __shfl_down_sync(0xffffffffu, v, off);
        if (lane == 0) s_pd[warp][i] = v;
    }
    __syncthreads();
    if (tid < 8) {
        float s = 0.f;
        #pragma unroll
        for (int w = 0; w < 8; w++) s += s_pd[w][tid];
        g_ad2[blockIdx.x * 8 + tid] = s;
    }
}

// ---------------- K_gemm2 (R9): xs2 = h1 @ w2s (2 nodes/warp), fused as2 ----------------
#define G2PITCH (H1 + 4)
__global__ void k_gemm2(const float* __restrict__ w2s, const float* __restrict__ a2s) {
    __shared__ __align__(16) float WsT[HID * G2PITCH];
    int tid = threadIdx.x;  // 256
    for (int i = tid; i < H1 * HID; i += 256) {
        int k = i >> 5, c = i & 31;
        WsT[c * G2PITCH + k] = w2s[i];
    }
    __syncthreads();
    int lane = tid & 31, warp = tid >> 5;
    int n0 = blockIdx.x * 16 + warp * 2;
    int n1 = n0 + 1;
    const float4* h40 = (const float4*)&g_out1[n0 * H1];
    const float4* h41 = (const float4*)&g_out1[n1 * H1];
    const float4* wr = (const float4*)&WsT[lane * G2PITCH];
    float acc0 = 0.f, acc1 = 0.f;
    #pragma unroll 8
    for (int k4 = 0; k4 < H1 / 4; k4++) {
        float4 a = __ldcs(&h40[k4]);
        float4 b = __ldcs(&h41[k4]);
        float4 wv = wr[k4];
        acc0 += a.x * wv.x + a.y * wv.y + a.z * wv.z + a.w * wv.w;
        acc1 += b.x * wv.x + b.y * wv.y + b.z * wv.z + b.w * wv.w;
    }
    g_xs2[n0 * HID + lane] = acc0;
    g_xs2[n1 * HID + lane] = acc1;
    float av = a2s[lane];
    float p0 = acc0 * av, p1 = acc1 * av;
    #pragma unroll
    for (int off = 16; off; off >>= 1) {
        p0 += __shfl_down_sync(0xffffffffu, p0, off);
        p1 += __shfl_down_sync(0xffffffffu, p1, off);
    }
    if (lane == 0) { g_as2[n0] = p0; g_as2[n1] = p1; }
}

// ---------------- K_agg2 (R10): single-pass gather (+b2), deep unroll ----------------
__global__ void k_agg2(const float* __restrict__ b2) {
    int lane = threadIdx.x & 31;
    int n = blockIdx.x * 8 + (threadIdx.x >> 5);
    if (n >= N_NODES) return;
    int beg = g_rowptr[n], end = g_rowptr[n + 1];
    float adn = g_ad2[n];
    int k = lane >> 3, j = lane & 7;
    float4 acc = {0, 0, 0, 0};
    float den = 0.f;
    int p = beg + k;
    for (; p + 12 < end; p += 16) {
        int s0 = __ldg(&g_perm_src[p]);
        int s1 = __ldg(&g_perm_src[p + 4]);
        int s2 = __ldg(&g_perm_src[p + 8]);
        int s3 = __ldg(&g_perm_src[p + 12]);
        float e0 = lrelu_exp(__ldg(&g_as2[s0]) + adn);
        float e1 = lrelu_exp(__ldg(&g_as2[s1]) + adn);
        float e2 = lrelu_exp(__ldg(&g_as2[s2]) + adn);
        float e3 = lrelu_exp(__ldg(&g_as2[s3]) + adn);
        float4 v0 = *(const float4*)&g_xs2[s0 * HID + j * 4];
        float4 v1 = *(const float4*)&g_xs2[s1 * HID + j * 4];
        float4 v2 = *(const float4*)&g_xs2[s2 * HID + j * 4];
        float4 v3 = *(const float4*)&g_xs2[s3 * HID + j * 4];
        den += (e0 + e1) + (e2 + e3);
        acc.x += v0.x * e0 + v1.x * e1 + v2.x * e2 + v3.x * e3;
        acc.y += v0.y * e0 + v1.y * e1 + v2.y * e2 + v3.y * e3;
        acc.z += v0.z * e0 + v1.z * e1 + v2.z * e2 + v3.z * e3;
        acc.w += v0.w * e0 + v1.w * e1 + v2.w * e2 + v3.w * e3;
    }
    for (; p < end; p += 4) {
        int s0 = __ldg(&g_perm_src[p]);
        float e0 = lrelu_exp(__ldg(&g_as2[s0]) + adn);
        float4 v0 = *(const float4*)&g_xs2[s0 * HID + j * 4];
        den += e0;
        acc.x += v0.x * e0; acc.y += v0.y * e0;
        acc.z += v0.z * e0; acc.w += v0.w * e0;
    }
    #pragma unroll
    for (int off = 8; off <= 16; off <<= 1) {
        acc.x += __shfl_xor_sync(0xffffffffu, acc.x, off);
        acc.y += __shfl_xor_sync(0xffffffffu, acc.y, off);
        acc.z += __shfl_xor_sync(0xffffffffu, acc.z, off);
        acc.w += __shfl_xor_sync(0xffffffffu, acc.w, off);
        den   += __shfl_xor_sync(0xffffffffu, den,   off);
    }
    if (lane < 8) {
        float r = 1.0f / (den + 1e-16f);
        float4 bb = *(const float4*)&b2[j * 4];
        acc.x = acc.x * r + bb.x; acc.y = acc.y * r + bb.y;
        acc.z = acc.z * r + bb.z; acc.w = acc.w * r + bb.w;
        *(float4*)&g_out2[n * HID + j * 4] = acc;
    }
}

// ---------------- K_pred (+ re-zero g_cnt for next replay) ----------------
__global__ void k_pred(const int* __restrict__ eli, float* __restrict__ out) {
    int l = blockIdx.x * blockDim.x + threadIdx.x;
    if (l < N_NODES) g_cnt[l] = 0;
    if (l >= N_LABEL) return;
    int a = eli[l], b = eli[N_LABEL + l];
    const float4* pa = (const float4*)&g_out2[a * HID];
    const float4* pb = (const float4*)&g_out2[b * HID];
    float acc = 0.f;
    #pragma unroll
    for (int i = 0; i < HID / 4; i++) {
        float4 va = pa[i], vb = pb[i];
        acc += va.x * vb.x + va.y * vb.y + va.z * vb.z + va.w * vb.w;
    }
    out[l] = acc;
}

// ---------------- launch: fork-join two independent chains ----------------
extern "C" void kernel_launch(void* const* d_in, const int* in_sizes, int n_in,
                              void* d_out, int out_size) {
    const float* x     = (const float*)d_in[0];
    const int*   ei    = (const int*)  d_in[1];
    const int*   eli   = (const int*)  d_in[2];
    const float* lin_w = (const float*)d_in[3];
    const float* lin_b = (const float*)d_in[4];
    const float* w1s   = (const float*)d_in[5];
    const float* w1d   = (const float*)d_in[6];
    const float* a1s   = (const float*)d_in[7];
    const float* a1d   = (const float*)d_in[8];
    const float* b1    = (const float*)d_in[9];
    const float* w2s   = (const float*)d_in[10];
    const float* w2d   = (const float*)d_in[11];
    const float* a2s   = (const float*)d_in[12];
    const float* a2d   = (const float*)d_in[13];
    const float* b2    = (const float*)d_in[14];
    float* out = (float*)d_out;

    cudaStream_t s2;
    cudaStreamCreateWithFlags(&s2, cudaStreamNonBlocking);
    cudaEvent_t e0, e1;
    cudaEventCreateWithFlags(&e0, cudaEventDisableTiming);
    cudaEventCreateWithFlags(&e1, cudaEventDisableTiming);

    // fork: chain B (prep -> lin) on s2
    cudaEventRecord(e0, 0);
    cudaStreamWaitEvent(s2, e0, 0);
    k_prep<<<1, 256, 0, s2>>>(w1d, a1d, w1s, a1s, w2d, a2d);
    k_lin<<<(N_NODES + 127) / 128, 256, 0, s2>>>(x, lin_w, lin_b);
    cudaEventRecord(e1, s2);

    // chain A (CSR build) on default stream
    k_hist<<<(N_EDGES + 1023) / 1024, 256>>>(ei);
    k_scan1<<<SCAN_BLOCKS, 256>>>();
    k_scan2<<<1, 256>>>();
    k_scan3<<<SCAN_BLOCKS, 256>>>();
    k_permute<<<(N_EDGES + 1023) / 1024, 256>>>(ei);

    // join
    cudaStreamWaitEvent(0, e1, 0);
    k_agg1<<<N_NODES / 8, 256>>>(w1s, b1);
    k_gemm2<<<N_NODES / 16, 256>>>(w2s, a2s);
    k_agg2<<<(N_NODES + 7) / 8, 256>>>(b2);
    k_pred<<<(N_LABEL + 255) / 256, 256>>>(eli, out);

    cudaEventDestroy(e0);
    cudaEventDestroy(e1);
    cudaStreamDestroy(s2);
}